// round 14
// baseline (speedup 1.0000x reference)
#include <cuda_runtime.h>
#include <math.h>

#define VV 400
#define VL 25600           // V*L
#define ALPHA 0.05f
#define ROWS 160000        // V*V

// ----------------------------- device scratch -----------------------------
__device__ float g_logits[2][ROWS];
__device__ float g_D[2][ROWS];
__device__ int   g_colCnt[2][VV];
__device__ int2  g_edges[2][VV][VV];      // (float-offset v*64, (1-a)*val)
__device__ float g_X1[104857600];         // [32 n][128 c][400 v][64 l]
__device__ float g_psum[102400];          // [3200 blk][32 ch]
__device__ float g_psq[102400];
__device__ float g_scale[32];
__device__ float g_shift[32];

// ----------------------------- K1: edge MLP -------------------------------
__global__ __launch_bounds__(256) void k_mlp(const float* __restrict__ adj,
        const float* __restrict__ w0, const float* __restrict__ b0,
        const float* __restrict__ w1, const float* __restrict__ b1,
        const float* __restrict__ w2, const float* __restrict__ b2) {
    extern __shared__ float sm[];
    float* s_w0t = sm;              // [128][64]
    float* s_w1  = sm + 8192;       // [128][64]
    float* s_b0  = sm + 16384;      // 128
    float* s_b1  = s_b0 + 128;      // 64
    float* s_w2  = s_b1 + 64;       // 128
    float* s_b2  = s_w2 + 128;      // 2
    int tid = threadIdx.x;

    for (int i = tid; i < 64 * 128; i += 256) {
        int k = i >> 7, m = i & 127;
        s_w0t[m * 64 + k] = w0[i];
    }
    for (int i = tid; i < 128 * 64; i += 256) s_w1[i] = w1[i];
    if (tid < 128) s_b0[tid] = b0[tid];
    if (tid < 64)  s_b1[tid] = b1[tid];
    if (tid < 128) s_w2[tid] = w2[tid];
    if (tid < 2)   s_b2[tid] = b2[tid];
    __syncthreads();

    int row = blockIdx.x * 256 + tid;
    if (row >= ROWS) return;

    float xin[64];
    const float4* ar = (const float4*)(adj + (size_t)row * 64);
#pragma unroll
    for (int k = 0; k < 16; k++) {
        float4 v = ar[k];
        xin[4*k] = v.x; xin[4*k+1] = v.y; xin[4*k+2] = v.z; xin[4*k+3] = v.w;
    }
    float h2[64];
#pragma unroll
    for (int j = 0; j < 64; j++) h2[j] = s_b1[j];

    for (int m = 0; m < 128; m++) {
        float h = s_b0[m];
        const float4* wc = (const float4*)(s_w0t + m * 64);
#pragma unroll
        for (int k = 0; k < 16; k++) {
            float4 w = wc[k];
            h += xin[4*k]*w.x + xin[4*k+1]*w.y + xin[4*k+2]*w.z + xin[4*k+3]*w.w;
        }
        h = fmaxf(h, 0.f);
        const float4* wr = (const float4*)(s_w1 + m * 64);
#pragma unroll
        for (int j = 0; j < 16; j++) {
            float4 w = wr[j];
            h2[4*j]   += h * w.x; h2[4*j+1] += h * w.y;
            h2[4*j+2] += h * w.z; h2[4*j+3] += h * w.w;
        }
    }
    float g0 = s_b2[0], g1 = s_b2[1];
#pragma unroll
    for (int j = 0; j < 64; j++) {
        float r = fmaxf(h2[j], 0.f);
        g0 += r * s_w2[2*j]; g1 += r * s_w2[2*j+1];
    }
    g_logits[0][row] = g0;
    g_logits[1][row] = g1;
}

// -------------------- K2: softmax + top-20 sparsify ------------------------
__global__ void k_sparsify() {
    int wid  = (blockIdx.x * blockDim.x + threadIdx.x) >> 5;
    int lane = threadIdx.x & 31;
    if (wid >= 800) return;
    int g = wid / VV, r = wid % VV;
    const float* lg = &g_logits[g][r * VV];

    float vals[13];
#pragma unroll
    for (int t = 0; t < 13; t++) {
        int j = lane + 32 * t;
        vals[t] = (j < VV) ? lg[j] : -1e30f;
    }
    float mx = -1e30f;
#pragma unroll
    for (int t = 0; t < 13; t++) mx = fmaxf(mx, vals[t]);
    for (int o = 16; o; o >>= 1) mx = fmaxf(mx, __shfl_xor_sync(~0u, mx, o));
    float se = 0.f;
#pragma unroll
    for (int t = 0; t < 13; t++) se += expf(vals[t] - mx);
    for (int o = 16; o; o >>= 1) se += __shfl_xor_sync(~0u, se, o);

    float* Drow = &g_D[g][r * VV];
#pragma unroll
    for (int t = 0; t < 13; t++) {
        int j = lane + 32 * t;
        if (j < VV) Drow[j] = 0.f;
    }

    unsigned used = 0;
    float selsum = 0.f, myP = 0.f;
    int myJ = -1;
    for (int it = 0; it < 20; it++) {
        float bv = -1e30f; int bj = 1 << 20;
#pragma unroll
        for (int t = 0; t < 13; t++)
            if (!((used >> t) & 1u) && vals[t] > bv) { bv = vals[t]; bj = lane + 32 * t; }
        for (int o = 16; o; o >>= 1) {
            float ov = __shfl_xor_sync(~0u, bv, o);
            int   oj = __shfl_xor_sync(~0u, bj, o);
            if (ov > bv || (ov == bv && oj < bj)) { bv = ov; bj = oj; }
        }
        if ((bj & 31) == lane) used |= 1u << (bj >> 5);
        float p = expf(bv - mx) / se;
        selsum += p;
        if (lane == it) { myJ = bj; myP = p; }
    }
    float inv = 1.f / (selsum + 1e-8f);
    if (lane < 20 && myJ >= 0 && myJ < VV) Drow[myJ] = myP * inv;
}

// -------------------- K2b: column-compact (CSC) edge lists -----------------
// Stores (v*64 float-offset, (1-alpha)*a) per column.
__global__ void k_csc() {
    int wid  = (blockIdx.x * blockDim.x + threadIdx.x) >> 5;
    int lane = threadIdx.x & 31;
    if (wid >= 800) return;
    int g = wid / VV, w = wid % VV;
    int cnt = 0;
    for (int base = 0; base < VV; base += 32) {
        int v = base + lane;
        float val = (v < VV) ? g_D[g][v * VV + w] : 0.f;
        unsigned bal = __ballot_sync(~0u, val != 0.f);
        if (val != 0.f) {
            int rank = __popc(bal & ((1u << lane) - 1u));
            g_edges[g][w][cnt + rank] = make_int2(v * 64, __float_as_int(val * (1.f - ALPHA)));
        }
        cnt += __popc(bal);
    }
    if (lane == 0) g_colCnt[g][w] = cnt;
}

// -------------------- K3: sparse graph propagation -------------------------
// 512 threads (16 warps) per CTA; per-warp smem edge staging, no shfl chains.
__device__ __forceinline__ void prop_pass(int g, const float* __restrict__ src,
                                          const float* __restrict__ Sx,
                                          float* dstS, float* __restrict__ dstG,
                                          int warp, int lane, int2* __restrict__ st) {
    const float* srcl = src + lane * 2;
    for (int w = warp; w < VV; w += 16) {
        float2 xa = *(const float2*)(Sx + w * 64 + lane * 2);
        float ax = ALPHA * xa.x, ay = ALPHA * xa.y;
        int cnt = g_colCnt[g][w];
        const int2* ep = &g_edges[g][w][0];
        for (int base = 0; base < cnt; base += 32) {
            int k = base + lane;
            if (k < cnt) st[lane] = __ldg(&ep[k]);
            __syncwarp();
            int m = min(32, cnt - base);
            int t = 0;
            for (; t + 4 <= m; t += 4) {
                int2 e0 = st[t], e1 = st[t+1], e2 = st[t+2], e3 = st[t+3];
                float2 x0 = *(const float2*)(srcl + e0.x);
                float2 x1 = *(const float2*)(srcl + e1.x);
                float2 x2 = *(const float2*)(srcl + e2.x);
                float2 x3 = *(const float2*)(srcl + e3.x);
                float a0 = __int_as_float(e0.y), a1 = __int_as_float(e1.y);
                float a2 = __int_as_float(e2.y), a3 = __int_as_float(e3.y);
                ax += a0 * x0.x; ay += a0 * x0.y;
                ax += a1 * x1.x; ay += a1 * x1.y;
                ax += a2 * x2.x; ay += a2 * x2.y;
                ax += a3 * x3.x; ay += a3 * x3.y;
            }
            for (; t < m; t++) {
                int2 e = st[t];
                float2 x = *(const float2*)(srcl + e.x);
                float a = __int_as_float(e.y);
                ax += a * x.x; ay += a * x.y;
            }
            __syncwarp();
        }
        float2 o; o.x = ax; o.y = ay;
        if (dstS) *(float2*)(dstS + w * 64 + lane * 2) = o;
        *(float2*)(dstG + w * 64 + lane * 2) = o;
    }
}

__global__ __launch_bounds__(512, 1) void k_prop(const float* __restrict__ inp) {
    extern __shared__ float sm[];
    float* Sx = sm;
    float* Sy = sm + VL;
    int2*  stage = (int2*)(sm + 2 * VL);   // [16 warps][32]
    int nc = blockIdx.x, n = nc >> 5, c = nc & 31;
    int tid = threadIdx.x, warp = tid >> 5, lane = tid & 31;
    int2* st = stage + warp * 32;

    const float4* xin = (const float4*)(inp + (size_t)nc * VL);
    for (int i = tid; i < VL / 4; i += 512) {
        float4 v = xin[i];
        v.x = fmaxf(v.x, 0.f); v.y = fmaxf(v.y, 0.f);
        v.z = fmaxf(v.z, 0.f); v.w = fmaxf(v.w, 0.f);
        ((float4*)Sx)[i] = v;
    }
    __syncthreads();

    float* X1n = g_X1 + (size_t)n * 128 * VL;
    for (int g = 0; g < 2; g++) {
        prop_pass(g, Sx, Sx, Sy, X1n + ((size_t)(2*g)*32 + c) * VL, warp, lane, st);
        __syncthreads();
        prop_pass(g, Sy, Sx, 0,  X1n + ((size_t)(2*g+1)*32 + c) * VL, warp, lane, st);
        __syncthreads();
    }
}

// -------------------- K4: 1x1 conv (160 -> 32) + BN partial sums ----------
__global__ __launch_bounds__(256) void k_conv(const float* __restrict__ inp,
        const float* __restrict__ cw, const float* __restrict__ cb,
        float* __restrict__ out) {
    __shared__ float sW[160 * 32];
    __shared__ float sB[32];
    __shared__ float rS[8 * 32], rQ[8 * 32];
    int tid = threadIdx.x;
    for (int i = tid; i < 160 * 32; i += 256) {
        int o = i / 160, cc = i % 160;
        sW[cc * 32 + o] = cw[i];
    }
    if (tid < 32) sB[tid] = cb[tid];
    __syncthreads();

    int n = blockIdx.y;
    int p = blockIdx.x * 256 + tid;
    const float* xi = inp  + (size_t)n * 32  * VL + p;
    const float* x1 = g_X1 + (size_t)n * 128 * VL + p;

    float acc[32];
#pragma unroll
    for (int o = 0; o < 32; o++) acc[o] = sB[o];

#pragma unroll 4
    for (int c = 0; c < 32; c++) {
        float x = fmaxf(xi[(size_t)c * VL], 0.f);
        const float4* w4 = (const float4*)(sW + c * 32);
#pragma unroll
        for (int q = 0; q < 8; q++) {
            float4 w = w4[q];
            acc[4*q]   += x * w.x; acc[4*q+1] += x * w.y;
            acc[4*q+2] += x * w.z; acc[4*q+3] += x * w.w;
        }
    }
#pragma unroll 4
    for (int c = 0; c < 128; c++) {
        float x = x1[(size_t)c * VL];
        const float4* w4 = (const float4*)(sW + (32 + c) * 32);
#pragma unroll
        for (int q = 0; q < 8; q++) {
            float4 w = w4[q];
            acc[4*q]   += x * w.x; acc[4*q+1] += x * w.y;
            acc[4*q+2] += x * w.z; acc[4*q+3] += x * w.w;
        }
    }

    float* op = out + (size_t)n * 32 * VL + p;
#pragma unroll
    for (int o = 0; o < 32; o++) op[(size_t)o * VL] = acc[o];

    int warp = tid >> 5, lane = tid & 31;
#pragma unroll
    for (int o = 0; o < 32; o++) {
        float v = acc[o], q = v * v;
        for (int off = 16; off; off >>= 1) {
            v += __shfl_xor_sync(~0u, v, off);
            q += __shfl_xor_sync(~0u, q, off);
        }
        if (lane == 0) { rS[o * 8 + warp] = v; rQ[o * 8 + warp] = q; }
    }
    __syncthreads();
    if (tid < 32) {
        float s = 0.f, q = 0.f;
#pragma unroll
        for (int w = 0; w < 8; w++) { s += rS[tid * 8 + w]; q += rQ[tid * 8 + w]; }
        int bid = blockIdx.y * gridDim.x + blockIdx.x;
        g_psum[bid * 32 + tid] = s;
        g_psq[bid * 32 + tid]  = q;
    }
}

// -------------------- K5: BN stats -> scale/shift ---------------------------
__global__ void k_bnstats(const float* __restrict__ gamma,
                          const float* __restrict__ beta) {
    int ch = threadIdx.x >> 5, lane = threadIdx.x & 31;   // 1024 threads
    float s = 0.f, q = 0.f;
    for (int i = lane; i < 3200; i += 32) {
        s += g_psum[i * 32 + ch];
        q += g_psq[i * 32 + ch];
    }
    for (int o = 16; o; o >>= 1) {
        s += __shfl_xor_sync(~0u, s, o);
        q += __shfl_xor_sync(~0u, q, o);
    }
    if (lane == 0) {
        const float invN = 1.f / 819200.f;
        float mean = s * invN;
        float var  = q * invN - mean * mean;
        float sc = gamma[ch] * rsqrtf(var + 1e-5f);
        g_scale[ch] = sc;
        g_shift[ch] = beta[ch] - mean * sc;
    }
}

// -------------------- K6: BN affine apply -----------------------------------
__global__ __launch_bounds__(256) void k_bnapply(float* __restrict__ out) {
    int i = blockIdx.x * 256 + threadIdx.x;   // float4 index, 6,553,600 total
    int o = (i / 6400) & 31;                  // VL/4 = 6400 float4 per (n,o)
    float sc = g_scale[o], sh = g_shift[o];
    float4* o4 = (float4*)out;
    float4 v = o4[i];
    v.x = v.x * sc + sh; v.y = v.y * sc + sh;
    v.z = v.z * sc + sh; v.w = v.w * sc + sh;
    o4[i] = v;
}

// ============================================================================
extern "C" void kernel_launch(void* const* d_in, const int* in_sizes, int n_in,
                              void* d_out, int out_size) {
    const float* inputs = (const float*)d_in[0];
    const float* adj    = (const float*)d_in[1];
    const float* w0 = (const float*)d_in[2];
    const float* b0 = (const float*)d_in[3];
    const float* w1 = (const float*)d_in[4];
    const float* b1 = (const float*)d_in[5];
    const float* w2 = (const float*)d_in[6];
    const float* b2 = (const float*)d_in[7];
    const float* cw = (const float*)d_in[8];
    const float* cb = (const float*)d_in[9];
    const float* gamma = (const float*)d_in[10];
    const float* beta  = (const float*)d_in[11];
    float* out = (float*)d_out;

    static int configured = 0;
    if (!configured) {
        cudaFuncSetAttribute(k_mlp,  cudaFuncAttributeMaxDynamicSharedMemorySize, 70000);
        cudaFuncSetAttribute(k_prop, cudaFuncAttributeMaxDynamicSharedMemorySize,
                             2 * VL * 4 + 16 * 32 * 8);
        configured = 1;
    }

    k_mlp<<<625, 256, 70000>>>(adj, w0, b0, w1, b1, w2, b2);
    k_sparsify<<<100, 256>>>();
    k_csc<<<100, 256>>>();
    k_prop<<<1024, 512, 2 * VL * 4 + 16 * 32 * 8>>>(inputs);
    dim3 gconv(100, 32);
    k_conv<<<gconv, 256>>>(inputs, cw, cb, out);
    k_bnstats<<<1, 1024>>>(gamma, beta);
    k_bnapply<<<25600, 256>>>(out);
}

// round 15
// speedup vs baseline: 1.1974x; 1.1974x over previous
#include <cuda_runtime.h>
#include <cuda_fp16.h>
#include <math.h>

#define VV 400
#define VL 25600           // V*L
#define ALPHA 0.05f
#define ROWS 160000        // V*V

// ----------------------------- device scratch -----------------------------
__device__ float g_logits[2][ROWS];
__device__ float g_D[2][ROWS];
__device__ int   g_colCnt[2][VV];
__device__ int2  g_edges[2][VV][VV];      // (half2-offset v*32, (1-a)*val)
__device__ float g_X1[104857600];         // [32 n][128 c][400 v][64 l]
__device__ float g_psum[51200];           // [1600 blk][32 ch]
__device__ float g_psq[51200];
__device__ float g_scale[32];
__device__ float g_shift[32];

// ----------------------------- K1: edge MLP -------------------------------
__global__ __launch_bounds__(256) void k_mlp(const float* __restrict__ adj,
        const float* __restrict__ w0, const float* __restrict__ b0,
        const float* __restrict__ w1, const float* __restrict__ b1,
        const float* __restrict__ w2, const float* __restrict__ b2) {
    extern __shared__ float sm[];
    float* s_w0t = sm;              // [128][64]
    float* s_w1  = sm + 8192;       // [128][64]
    float* s_b0  = sm + 16384;      // 128
    float* s_b1  = s_b0 + 128;      // 64
    float* s_w2  = s_b1 + 64;       // 128
    float* s_b2  = s_w2 + 128;      // 2
    int tid = threadIdx.x;

    for (int i = tid; i < 64 * 128; i += 256) {
        int k = i >> 7, m = i & 127;
        s_w0t[m * 64 + k] = w0[i];
    }
    for (int i = tid; i < 128 * 64; i += 256) s_w1[i] = w1[i];
    if (tid < 128) s_b0[tid] = b0[tid];
    if (tid < 64)  s_b1[tid] = b1[tid];
    if (tid < 128) s_w2[tid] = w2[tid];
    if (tid < 2)   s_b2[tid] = b2[tid];
    __syncthreads();

    int row = blockIdx.x * 256 + tid;
    if (row >= ROWS) return;

    float xin[64];
    const float4* ar = (const float4*)(adj + (size_t)row * 64);
#pragma unroll
    for (int k = 0; k < 16; k++) {
        float4 v = ar[k];
        xin[4*k] = v.x; xin[4*k+1] = v.y; xin[4*k+2] = v.z; xin[4*k+3] = v.w;
    }
    float h2[64];
#pragma unroll
    for (int j = 0; j < 64; j++) h2[j] = s_b1[j];

    for (int m = 0; m < 128; m++) {
        float h = s_b0[m];
        const float4* wc = (const float4*)(s_w0t + m * 64);
#pragma unroll
        for (int k = 0; k < 16; k++) {
            float4 w = wc[k];
            h += xin[4*k]*w.x + xin[4*k+1]*w.y + xin[4*k+2]*w.z + xin[4*k+3]*w.w;
        }
        h = fmaxf(h, 0.f);
        const float4* wr = (const float4*)(s_w1 + m * 64);
#pragma unroll
        for (int j = 0; j < 16; j++) {
            float4 w = wr[j];
            h2[4*j]   += h * w.x; h2[4*j+1] += h * w.y;
            h2[4*j+2] += h * w.z; h2[4*j+3] += h * w.w;
        }
    }
    float g0 = s_b2[0], g1 = s_b2[1];
#pragma unroll
    for (int j = 0; j < 64; j++) {
        float r = fmaxf(h2[j], 0.f);
        g0 += r * s_w2[2*j]; g1 += r * s_w2[2*j+1];
    }
    g_logits[0][row] = g0;
    g_logits[1][row] = g1;
}

// -------------------- K2: softmax + top-20 sparsify ------------------------
__global__ void k_sparsify() {
    int wid  = (blockIdx.x * blockDim.x + threadIdx.x) >> 5;
    int lane = threadIdx.x & 31;
    if (wid >= 800) return;
    int g = wid / VV, r = wid % VV;
    const float* lg = &g_logits[g][r * VV];

    float vals[13];
#pragma unroll
    for (int t = 0; t < 13; t++) {
        int j = lane + 32 * t;
        vals[t] = (j < VV) ? lg[j] : -1e30f;
    }
    float mx = -1e30f;
#pragma unroll
    for (int t = 0; t < 13; t++) mx = fmaxf(mx, vals[t]);
    for (int o = 16; o; o >>= 1) mx = fmaxf(mx, __shfl_xor_sync(~0u, mx, o));
    float se = 0.f;
#pragma unroll
    for (int t = 0; t < 13; t++) se += expf(vals[t] - mx);
    for (int o = 16; o; o >>= 1) se += __shfl_xor_sync(~0u, se, o);

    float* Drow = &g_D[g][r * VV];
#pragma unroll
    for (int t = 0; t < 13; t++) {
        int j = lane + 32 * t;
        if (j < VV) Drow[j] = 0.f;
    }

    unsigned used = 0;
    float selsum = 0.f, myP = 0.f;
    int myJ = -1;
    for (int it = 0; it < 20; it++) {
        float bv = -1e30f; int bj = 1 << 20;
#pragma unroll
        for (int t = 0; t < 13; t++)
            if (!((used >> t) & 1u) && vals[t] > bv) { bv = vals[t]; bj = lane + 32 * t; }
        for (int o = 16; o; o >>= 1) {
            float ov = __shfl_xor_sync(~0u, bv, o);
            int   oj = __shfl_xor_sync(~0u, bj, o);
            if (ov > bv || (ov == bv && oj < bj)) { bv = ov; bj = oj; }
        }
        if ((bj & 31) == lane) used |= 1u << (bj >> 5);
        float p = expf(bv - mx) / se;
        selsum += p;
        if (lane == it) { myJ = bj; myP = p; }
    }
    float inv = 1.f / (selsum + 1e-8f);
    if (lane < 20 && myJ >= 0 && myJ < VV) Drow[myJ] = myP * inv;
}

// -------------------- K2b: column-compact (CSC) edge lists -----------------
// Stores (v*32 half2-offset, (1-alpha)*a) per column.
__global__ void k_csc() {
    int wid  = (blockIdx.x * blockDim.x + threadIdx.x) >> 5;
    int lane = threadIdx.x & 31;
    if (wid >= 800) return;
    int g = wid / VV, w = wid % VV;
    int cnt = 0;
    for (int base = 0; base < VV; base += 32) {
        int v = base + lane;
        float val = (v < VV) ? g_D[g][v * VV + w] : 0.f;
        unsigned bal = __ballot_sync(~0u, val != 0.f);
        if (val != 0.f) {
            int rank = __popc(bal & ((1u << lane) - 1u));
            g_edges[g][w][cnt + rank] = make_int2(v * 32, __float_as_int(val * (1.f - ALPHA)));
        }
        cnt += __popc(bal);
    }
    if (lane == 0) g_colCnt[g][w] = cnt;
}

// -------------------- K3: sparse graph propagation (fp16 smem) -------------
__device__ __forceinline__ void prop_pass(int g, const __half2* __restrict__ src,
                                          const __half2* __restrict__ Sx2,
                                          __half2* dstS, float* __restrict__ dstG,
                                          int warp, int lane, int2* __restrict__ st) {
    const __half2* srcl = src + lane;
    for (int w = warp; w < VV; w += 16) {
        float2 xa = __half22float2(Sx2[w * 32 + lane]);
        float ax = ALPHA * xa.x, ay = ALPHA * xa.y;
        int cnt = g_colCnt[g][w];
        const int2* ep = &g_edges[g][w][0];
        for (int base = 0; base < cnt; base += 32) {
            int k = base + lane;
            if (k < cnt) st[lane] = __ldg(&ep[k]);
            __syncwarp();
            int m = min(32, cnt - base);
            int t = 0;
            for (; t + 4 <= m; t += 4) {
                int2 e0 = st[t], e1 = st[t+1], e2 = st[t+2], e3 = st[t+3];
                float2 x0 = __half22float2(srcl[e0.x]);
                float2 x1 = __half22float2(srcl[e1.x]);
                float2 x2 = __half22float2(srcl[e2.x]);
                float2 x3 = __half22float2(srcl[e3.x]);
                float a0 = __int_as_float(e0.y), a1 = __int_as_float(e1.y);
                float a2 = __int_as_float(e2.y), a3 = __int_as_float(e3.y);
                ax += a0 * x0.x; ay += a0 * x0.y;
                ax += a1 * x1.x; ay += a1 * x1.y;
                ax += a2 * x2.x; ay += a2 * x2.y;
                ax += a3 * x3.x; ay += a3 * x3.y;
            }
            for (; t < m; t++) {
                int2 e = st[t];
                float2 x = __half22float2(srcl[e.x]);
                float a = __int_as_float(e.y);
                ax += a * x.x; ay += a * x.y;
            }
            __syncwarp();
        }
        if (dstS) dstS[w * 32 + lane] = __floats2half2_rn(ax, ay);
        float2 o; o.x = ax; o.y = ay;
        *(float2*)(dstG + w * 64 + lane * 2) = o;
    }
}

__global__ __launch_bounds__(512, 2) void k_prop(const float* __restrict__ inp) {
    extern __shared__ float sm[];
    __half2* Sx2 = (__half2*)sm;                          // VV*32 half2 = 51200B
    __half2* Sy2 = Sx2 + VV * 32;                         // 51200B
    int2*  stage = (int2*)(Sy2 + VV * 32);                // 16*32*8 = 4096B
    int nc = blockIdx.x, n = nc >> 5, c = nc & 31;
    int tid = threadIdx.x, warp = tid >> 5, lane = tid & 31;
    int2* st = stage + warp * 32;

    const float4* xin = (const float4*)(inp + (size_t)nc * VL);
    for (int i = tid; i < VL / 4; i += 512) {
        float4 v = xin[i];
        v.x = fmaxf(v.x, 0.f); v.y = fmaxf(v.y, 0.f);
        v.z = fmaxf(v.z, 0.f); v.w = fmaxf(v.w, 0.f);
        Sx2[2*i]   = __floats2half2_rn(v.x, v.y);
        Sx2[2*i+1] = __floats2half2_rn(v.z, v.w);
    }
    __syncthreads();

    float* X1n = g_X1 + (size_t)n * 128 * VL;
    for (int g = 0; g < 2; g++) {
        prop_pass(g, Sx2, Sx2, Sy2, X1n + ((size_t)(2*g)*32 + c) * VL, warp, lane, st);
        __syncthreads();
        prop_pass(g, Sy2, Sx2, 0,   X1n + ((size_t)(2*g+1)*32 + c) * VL, warp, lane, st);
        __syncthreads();
    }
}

// -------------------- K4: 1x1 conv (160 -> 32) + BN partial sums ----------
// 2 positions per thread; grid (50, 32).
__global__ __launch_bounds__(256) void k_conv(const float* __restrict__ inp,
        const float* __restrict__ cw, const float* __restrict__ cb,
        float* __restrict__ out) {
    __shared__ float sW[160 * 32];
    __shared__ float sB[32];
    __shared__ float rS[8 * 32], rQ[8 * 32];
    int tid = threadIdx.x;
    for (int i = tid; i < 160 * 32; i += 256) {
        int o = i / 160, cc = i % 160;
        sW[cc * 32 + o] = cw[i];
    }
    if (tid < 32) sB[tid] = cb[tid];
    __syncthreads();

    int n = blockIdx.y;
    int p = blockIdx.x * 512 + tid;          // p and p+256
    const float* xi = inp  + (size_t)n * 32  * VL + p;
    const float* x1 = g_X1 + (size_t)n * 128 * VL + p;

    float acc0[32], acc1[32];
#pragma unroll
    for (int o = 0; o < 32; o++) { acc0[o] = sB[o]; acc1[o] = sB[o]; }

#pragma unroll 2
    for (int c = 0; c < 32; c++) {
        float xa = fmaxf(xi[(size_t)c * VL], 0.f);
        float xb = fmaxf(xi[(size_t)c * VL + 256], 0.f);
        const float4* w4 = (const float4*)(sW + c * 32);
#pragma unroll
        for (int q = 0; q < 8; q++) {
            float4 w = w4[q];
            acc0[4*q]   += xa * w.x; acc0[4*q+1] += xa * w.y;
            acc0[4*q+2] += xa * w.z; acc0[4*q+3] += xa * w.w;
            acc1[4*q]   += xb * w.x; acc1[4*q+1] += xb * w.y;
            acc1[4*q+2] += xb * w.z; acc1[4*q+3] += xb * w.w;
        }
    }
#pragma unroll 2
    for (int c = 0; c < 128; c++) {
        float xa = x1[(size_t)c * VL];
        float xb = x1[(size_t)c * VL + 256];
        const float4* w4 = (const float4*)(sW + (32 + c) * 32);
#pragma unroll
        for (int q = 0; q < 8; q++) {
            float4 w = w4[q];
            acc0[4*q]   += xa * w.x; acc0[4*q+1] += xa * w.y;
            acc0[4*q+2] += xa * w.z; acc0[4*q+3] += xa * w.w;
            acc1[4*q]   += xb * w.x; acc1[4*q+1] += xb * w.y;
            acc1[4*q+2] += xb * w.z; acc1[4*q+3] += xb * w.w;
        }
    }

    float* op = out + (size_t)n * 32 * VL + p;
#pragma unroll
    for (int o = 0; o < 32; o++) {
        op[(size_t)o * VL]       = acc0[o];
        op[(size_t)o * VL + 256] = acc1[o];
    }

    int warp = tid >> 5, lane = tid & 31;
#pragma unroll
    for (int o = 0; o < 32; o++) {
        float v = acc0[o] + acc1[o];
        float q = acc0[o] * acc0[o] + acc1[o] * acc1[o];
        for (int off = 16; off; off >>= 1) {
            v += __shfl_xor_sync(~0u, v, off);
            q += __shfl_xor_sync(~0u, q, off);
        }
        if (lane == 0) { rS[o * 8 + warp] = v; rQ[o * 8 + warp] = q; }
    }
    __syncthreads();
    if (tid < 32) {
        float s = 0.f, q = 0.f;
#pragma unroll
        for (int w = 0; w < 8; w++) { s += rS[tid * 8 + w]; q += rQ[tid * 8 + w]; }
        int bid = blockIdx.y * gridDim.x + blockIdx.x;
        g_psum[bid * 32 + tid] = s;
        g_psq[bid * 32 + tid]  = q;
    }
}

// -------------------- K5: BN stats -> scale/shift ---------------------------
__global__ void k_bnstats(const float* __restrict__ gamma,
                          const float* __restrict__ beta) {
    int ch = threadIdx.x >> 5, lane = threadIdx.x & 31;   // 1024 threads
    float s = 0.f, q = 0.f;
    for (int i = lane; i < 1600; i += 32) {
        s += g_psum[i * 32 + ch];
        q += g_psq[i * 32 + ch];
    }
    for (int o = 16; o; o >>= 1) {
        s += __shfl_xor_sync(~0u, s, o);
        q += __shfl_xor_sync(~0u, q, o);
    }
    if (lane == 0) {
        const float invN = 1.f / 819200.f;
        float mean = s * invN;
        float var  = q * invN - mean * mean;
        float sc = gamma[ch] * rsqrtf(var + 1e-5f);
        g_scale[ch] = sc;
        g_shift[ch] = beta[ch] - mean * sc;
    }
}

// -------------------- K6: BN affine apply -----------------------------------
__global__ __launch_bounds__(256) void k_bnapply(float* __restrict__ out) {
    int i = blockIdx.x * 256 + threadIdx.x;   // float4 index, 6,553,600 total
    int o = (i / 6400) & 31;                  // VL/4 = 6400 float4 per (n,o)
    float sc = g_scale[o], sh = g_shift[o];
    float4* o4 = (float4*)out;
    float4 v = o4[i];
    v.x = v.x * sc + sh; v.y = v.y * sc + sh;
    v.z = v.z * sc + sh; v.w = v.w * sc + sh;
    o4[i] = v;
}

// ============================================================================
extern "C" void kernel_launch(void* const* d_in, const int* in_sizes, int n_in,
                              void* d_out, int out_size) {
    const float* inputs = (const float*)d_in[0];
    const float* adj    = (const float*)d_in[1];
    const float* w0 = (const float*)d_in[2];
    const float* b0 = (const float*)d_in[3];
    const float* w1 = (const float*)d_in[4];
    const float* b1 = (const float*)d_in[5];
    const float* w2 = (const float*)d_in[6];
    const float* b2 = (const float*)d_in[7];
    const float* cw = (const float*)d_in[8];
    const float* cb = (const float*)d_in[9];
    const float* gamma = (const float*)d_in[10];
    const float* beta  = (const float*)d_in[11];
    float* out = (float*)d_out;

    const int PROP_SMEM = VV * 32 * 4 * 2 + 16 * 32 * 8;   // 106496 B

    static int configured = 0;
    if (!configured) {
        cudaFuncSetAttribute(k_mlp,  cudaFuncAttributeMaxDynamicSharedMemorySize, 70000);
        cudaFuncSetAttribute(k_prop, cudaFuncAttributeMaxDynamicSharedMemorySize, PROP_SMEM);
        configured = 1;
    }

    k_mlp<<<625, 256, 70000>>>(adj, w0, b0, w1, b1, w2, b2);
    k_sparsify<<<100, 256>>>();
    k_csc<<<100, 256>>>();
    k_prop<<<1024, 512, PROP_SMEM>>>(inputs);
    dim3 gconv(50, 32);
    k_conv<<<gconv, 256>>>(inputs, cw, cb, out);
    k_bnstats<<<1, 1024>>>(gamma, beta);
    k_bnapply<<<25600, 256>>>(out);
}